// round 2
// baseline (speedup 1.0000x reference)
#include <cuda_runtime.h>
#include <cstdint>
#include <cstddef>

#define T_STEPS 256
#define BATCH   64
#define DIN     512
#define R       2048
#define DOUT    128
#define NW      (R*R)            // 4194304
#define KEEPK   838860u          // max(1, int(NW * (1-0.8)))
#define BETA    0.9f
#define KS      16               // K-split for step GEMM
#define KSL     (R/KS)           // 128

// ---------------- device scratch (static, no allocation) ----------------
__device__ float      g_weff [NW];                                  // 16 MB
__device__ float      g_drive[(size_t)T_STEPS*BATCH*R];             // 128 MB
__device__ float      g_part [(size_t)KS*BATCH*R];                  // 8 MB
__device__ float      g_V    [BATCH*R];
__device__ float      g_St   [R*BATCH];                             // spikes transposed [i][b]
__device__ unsigned   g_bits [(size_t)T_STEPS*BATCH*(R/32)];        // 4 MB spike bitmasks
__device__ unsigned   g_hist1[65536];
__device__ unsigned   g_hist2[65536];
__device__ unsigned   g_bucket;
__device__ unsigned   g_krem;
__device__ unsigned   g_cntabove;
__device__ float      g_thresh;
__device__ float      g_active_ratio;
__device__ unsigned long long g_spk;

// ---------------- threshold selection (exact, 2-pass radix) ----------------
__global__ void hist1_k(const float* __restrict__ w) {
    unsigned i = blockIdx.x * blockDim.x + threadIdx.x;
    unsigned stride = gridDim.x * blockDim.x;
    for (; i < NW; i += stride) {
        unsigned key = __float_as_uint(w[i]) & 0x7fffffffu;
        atomicAdd(&g_hist1[key >> 16], 1u);
    }
}

__global__ void sel1_k() {
    __shared__ unsigned ssum[1024];
    int t = threadIdx.x;
    unsigned s = 0;
    for (int j = 0; j < 64; j++) s += g_hist1[t*64 + j];
    ssum[t] = s;
    __syncthreads();
    if (t == 0) {
        unsigned long long cum = 0;
        int c = 1023;
        for (; c >= 0; c--) {
            if (cum + ssum[c] >= (unsigned long long)KEEPK) break;
            cum += ssum[c];
        }
        unsigned bucket = 0;
        for (int j = 63; j >= 0; j--) {
            unsigned h = g_hist1[c*64 + j];
            if (cum + h >= (unsigned long long)KEEPK) { bucket = (unsigned)(c*64 + j); break; }
            cum += h;
        }
        g_bucket   = bucket;
        g_cntabove = (unsigned)cum;            // count with top16 strictly above bucket
        g_krem     = KEEPK - (unsigned)cum;    // rank remaining inside bucket
    }
}

__global__ void hist2_k(const float* __restrict__ w) {
    unsigned bucket = g_bucket;
    unsigned i = blockIdx.x * blockDim.x + threadIdx.x;
    unsigned stride = gridDim.x * blockDim.x;
    for (; i < NW; i += stride) {
        unsigned key = __float_as_uint(w[i]) & 0x7fffffffu;
        if ((key >> 16) == bucket) atomicAdd(&g_hist2[key & 0xffffu], 1u);
    }
}

__global__ void sel2_k() {
    __shared__ unsigned ssum[1024];
    int t = threadIdx.x;
    unsigned s = 0;
    for (int j = 0; j < 64; j++) s += g_hist2[t*64 + j];
    ssum[t] = s;
    __syncthreads();
    if (t == 0) {
        unsigned krem = g_krem;
        unsigned long long cum = 0;
        int c = 1023;
        for (; c >= 0; c--) {
            if (cum + ssum[c] >= (unsigned long long)krem) break;
            cum += ssum[c];
        }
        unsigned low = 0;
        for (int j = 63; j >= 0; j--) {
            unsigned h = g_hist2[c*64 + j];
            cum += h;
            if (cum >= (unsigned long long)krem) { low = (unsigned)(c*64 + j); break; }
        }
        unsigned bits = (g_bucket << 16) | low;
        g_thresh = __uint_as_float(bits);
        unsigned long long cnt_ge = (unsigned long long)g_cntabove + cum;
        g_active_ratio = (float)((double)cnt_ge / (double)NW);
    }
}

__global__ void weff_k(const float* __restrict__ w) {
    float th = g_thresh;
    unsigned i = blockIdx.x * blockDim.x + threadIdx.x;
    if (i < NW) {
        float v = w[i];
        g_weff[i] = (fabsf(v) >= th) ? v : 0.0f;
    }
}

// ---------------- input projection: drive = x @ w_in + b_in ----------------
// C[M=16384][N=2048], K=512. 64x64 tile, 256 threads, 4x4 per thread.
#define BM 64
#define BN 64
#define BK 16
__global__ void __launch_bounds__(256) drive_k(const float* __restrict__ A,
                                               const float* __restrict__ Bw,
                                               const float* __restrict__ bias) {
    __shared__ float sA[BK][BM + 1];
    __shared__ float sB[BK][BN + 1];
    int bm = blockIdx.y * BM;
    int bn = blockIdx.x * BN;
    int tid = threadIdx.x;
    int tx = tid & 15, ty = tid >> 4;
    float acc[4][4] = {};
    for (int k0 = 0; k0 < DIN; k0 += BK) {
        #pragma unroll
        for (int e = 0; e < 4; e++) {
            int idx = tid + e * 256;
            int m = idx >> 4, k = idx & 15;
            sA[k][m] = A[(size_t)(bm + m) * DIN + k0 + k];
        }
        #pragma unroll
        for (int e = 0; e < 4; e++) {
            int idx = tid + e * 256;
            int k = idx >> 6, n = idx & 63;
            sB[k][n] = Bw[(size_t)(k0 + k) * R + bn + n];
        }
        __syncthreads();
        #pragma unroll
        for (int k = 0; k < BK; k++) {
            float a[4], b[4];
            #pragma unroll
            for (int u = 0; u < 4; u++) a[u] = sA[k][ty*4 + u];
            #pragma unroll
            for (int u = 0; u < 4; u++) b[u] = sB[k][tx*4 + u];
            #pragma unroll
            for (int i = 0; i < 4; i++)
                #pragma unroll
                for (int j = 0; j < 4; j++)
                    acc[i][j] += a[i] * b[j];
        }
        __syncthreads();
    }
    #pragma unroll
    for (int i = 0; i < 4; i++)
        #pragma unroll
        for (int j = 0; j < 4; j++)
            g_drive[(size_t)(bm + ty*4 + i) * R + bn + tx*4 + j] = acc[i][j] + bias[bn + tx*4 + j];
}

// ---------------- recurrent step: phase A  (partial = s_prev @ W_eff, K-split) ----------------
// grid (4 jtiles, 4 bgroups, KS), 128 threads; thread owns 4 j cols x 16 batches.
__device__ __forceinline__ void fma4(float4& a, float s, const float4& w) {
    a.x += s * w.x; a.y += s * w.y; a.z += s * w.z; a.w += s * w.w;
}

__global__ void __launch_bounds__(128) stepA_k() {
    __shared__ __align__(16) float ssh[KSL][16];
    int jt = blockIdx.x, bg = blockIdx.y, ks = blockIdx.z;
    int tid = threadIdx.x;
    int j0 = jt * 512 + tid * 4;
    int i0 = ks * KSL;

    for (int e = tid; e < KSL * 16; e += 128) {
        int i = e >> 4, bb = e & 15;
        ssh[i][bb] = g_St[(size_t)(i0 + i) * BATCH + bg * 16 + bb];
    }
    __syncthreads();

    float4 acc[16];
    #pragma unroll
    for (int bb = 0; bb < 16; bb++) acc[bb] = make_float4(0.f, 0.f, 0.f, 0.f);

    const float* wrow = &g_weff[(size_t)i0 * R + j0];
    #pragma unroll 4
    for (int i = 0; i < KSL; i++) {
        float4 w = *reinterpret_cast<const float4*>(wrow);
        wrow += R;
        const float4* sp = reinterpret_cast<const float4*>(&ssh[i][0]);
        float4 s0 = sp[0], s1 = sp[1], s2 = sp[2], s3 = sp[3];
        fma4(acc[0],  s0.x, w); fma4(acc[1],  s0.y, w); fma4(acc[2],  s0.z, w); fma4(acc[3],  s0.w, w);
        fma4(acc[4],  s1.x, w); fma4(acc[5],  s1.y, w); fma4(acc[6],  s1.z, w); fma4(acc[7],  s1.w, w);
        fma4(acc[8],  s2.x, w); fma4(acc[9],  s2.y, w); fma4(acc[10], s2.z, w); fma4(acc[11], s2.w, w);
        fma4(acc[12], s3.x, w); fma4(acc[13], s3.y, w); fma4(acc[14], s3.z, w); fma4(acc[15], s3.w, w);
    }
    #pragma unroll
    for (int bb = 0; bb < 16; bb++) {
        *reinterpret_cast<float4*>(&g_part[((size_t)ks * BATCH + bg * 16 + bb) * R + j0]) = acc[bb];
    }
}

// ---------------- recurrent step: phase B  (reduce + LIF + spike) ----------------
__global__ void __launch_bounds__(256) stepB_k(int t) {
    int idx = blockIdx.x * 256 + threadIdx.x;     // 0..131071
    int b = idx >> 11;
    int j = idx & (R - 1);

    float sum = g_drive[((size_t)t * BATCH + b) * R + j];
    #pragma unroll
    for (int ks = 0; ks < KS; ks++)
        sum += g_part[((size_t)ks * BATCH + b) * R + j];

    float V = BETA * g_V[idx] + sum;
    float s = (V > 1.0f) ? 1.0f : 0.0f;
    V -= s;
    g_V[idx] = V;
    g_St[(size_t)j * BATCH + b] = s;

    unsigned ballot = __ballot_sync(0xffffffffu, s != 0.0f);
    __shared__ int ssum;
    if (threadIdx.x == 0) ssum = 0;
    __syncthreads();
    if ((threadIdx.x & 31) == 0) {
        g_bits[((size_t)t * BATCH + b) * (R / 32) + (j >> 5)] = ballot;
        atomicAdd(&ssum, __popc(ballot));
    }
    __syncthreads();
    if (threadIdx.x == 0) atomicAdd(&g_spk, (unsigned long long)ssum);
}

// ---------------- logits for all (t,b) from spike bitmasks ----------------
__global__ void __launch_bounds__(128) logits_k(const float* __restrict__ wh,
                                                const float* __restrict__ bh,
                                                float* __restrict__ out) {
    int tb = blockIdx.x;      // t*64 + b
    int d = threadIdx.x;
    __shared__ unsigned bits[64];
    if (d < 64) bits[d] = g_bits[(size_t)tb * 64 + d];
    __syncthreads();
    float acc = bh[d];
    #pragma unroll 1
    for (int w = 0; w < 64; w++) {
        unsigned m = bits[w];
        while (m) {                 // uniform across warp (m from shared)
            int k = __ffs(m) - 1;
            m &= m - 1;
            acc += wh[(size_t)(w * 32 + k) * DOUT + d];
        }
    }
    out[(size_t)tb * DOUT + d] = acc;
}

// ---------------- readout = mean over T ----------------
__global__ void readout_k(const float* __restrict__ logits, float* __restrict__ out) {
    int idx = blockIdx.x * 256 + threadIdx.x;   // 0..8191
    if (idx < BATCH * DOUT) {
        float s = 0.f;
        for (int t = 0; t < T_STEPS; t++) s += logits[(size_t)t * BATCH * DOUT + idx];
        out[idx] = s * (1.0f / T_STEPS);
    }
}

__global__ void scalars_k(float* __restrict__ out) {
    out[0] = (float)((double)g_spk / (double)((size_t)T_STEPS * BATCH * R)); // spike_rate
    out[1] = g_active_ratio;                                                 // active_ratio
}

// ---------------- launch ----------------
extern "C" void kernel_launch(void* const* d_in, const int* in_sizes, int n_in,
                              void* d_out, int out_size) {
    const float* x      = (const float*)d_in[0];
    const float* w_in   = (const float*)d_in[1];
    const float* b_in   = (const float*)d_in[2];
    const float* w_rec  = (const float*)d_in[3];
    const float* w_head = (const float*)d_in[4];
    const float* b_head = (const float*)d_in[5];
    float* out = (float*)d_out;

    void *h1p, *h2p, *vp, *stp, *spkp;
    cudaGetSymbolAddress(&h1p,  g_hist1);
    cudaGetSymbolAddress(&h2p,  g_hist2);
    cudaGetSymbolAddress(&vp,   g_V);
    cudaGetSymbolAddress(&stp,  g_St);
    cudaGetSymbolAddress(&spkp, g_spk);

    cudaMemsetAsync(h1p,  0, 65536 * sizeof(unsigned));
    cudaMemsetAsync(h2p,  0, 65536 * sizeof(unsigned));
    cudaMemsetAsync(vp,   0, BATCH * R * sizeof(float));
    cudaMemsetAsync(stp,  0, R * BATCH * sizeof(float));
    cudaMemsetAsync(spkp, 0, sizeof(unsigned long long));

    // exact top-k threshold
    hist1_k<<<2048, 512>>>(w_rec);
    sel1_k<<<1, 1024>>>();
    hist2_k<<<2048, 512>>>(w_rec);
    sel2_k<<<1, 1024>>>();
    weff_k<<<NW / 256, 256>>>(w_rec);

    // input projection
    drive_k<<<dim3(R / BN, (T_STEPS * BATCH) / BM), 256>>>(x, w_in, b_in);

    // sequential LIF scan
    for (int t = 0; t < T_STEPS; t++) {
        stepA_k<<<dim3(4, 4, KS), 128>>>();
        stepB_k<<<(BATCH * R) / 256, 256>>>(t);
    }

    // outputs: [readout 8192][logits_seq 2097152][spike_rate 1][active_ratio 1]
    float* logits_out = out + BATCH * DOUT;
    logits_k<<<T_STEPS * BATCH, 128>>>(w_head, b_head, logits_out);
    readout_k<<<(BATCH * DOUT + 255) / 256, 256>>>(logits_out, out);
    scalars_k<<<1, 1>>>(out + BATCH * DOUT + (size_t)T_STEPS * BATCH * DOUT);
}

// round 5
// speedup vs baseline: 1.0020x; 1.0020x over previous
#include <cuda_runtime.h>
#include <cstdint>
#include <cstddef>

#define T_STEPS 256
#define BATCH   64
#define DIN     512
#define R       2048
#define DOUT    128
#define NW      (R*R)            // 4194304
#define KEEPK   838860u          // max(1, int(NW * (1-0.8)))
#define BETA    0.9f
#define KS      16               // K-split for step GEMM
#define KSL     (R/KS)           // 128

// ---------------- device scratch (static, no allocation) ----------------
__device__ float      g_weff [NW];                                  // 16 MB
__device__ float      g_drive[(size_t)T_STEPS*BATCH*R];             // 128 MB
__device__ float      g_part [(size_t)KS*BATCH*R];                  // 8 MB
__device__ float      g_V    [BATCH*R];
__device__ float      g_St   [R*BATCH];                             // spikes transposed [i][b]
__device__ unsigned   g_bits [(size_t)T_STEPS*BATCH*(R/32)];        // 4 MB spike bitmasks
__device__ unsigned   g_hist1[65536];
__device__ unsigned   g_hist2[65536];
__device__ unsigned   g_bucket;
__device__ unsigned   g_krem;
__device__ unsigned   g_cntabove;
__device__ float      g_thresh;
__device__ float      g_active_ratio;
__device__ unsigned long long g_spk;

// ---------------- threshold selection (exact, 2-pass radix) ----------------
__global__ void hist1_k(const float* __restrict__ w) {
    unsigned i = blockIdx.x * blockDim.x + threadIdx.x;
    unsigned stride = gridDim.x * blockDim.x;
    for (; i < NW; i += stride) {
        unsigned key = __float_as_uint(w[i]) & 0x7fffffffu;
        atomicAdd(&g_hist1[key >> 16], 1u);
    }
}

__global__ void sel1_k() {
    __shared__ unsigned ssum[1024];
    int t = threadIdx.x;
    unsigned s = 0;
    for (int j = 0; j < 64; j++) s += g_hist1[t*64 + j];
    ssum[t] = s;
    __syncthreads();
    if (t == 0) {
        unsigned long long cum = 0;
        int c = 1023;
        for (; c >= 0; c--) {
            if (cum + ssum[c] >= (unsigned long long)KEEPK) break;
            cum += ssum[c];
        }
        unsigned bucket = 0;
        for (int j = 63; j >= 0; j--) {
            unsigned h = g_hist1[c*64 + j];
            if (cum + h >= (unsigned long long)KEEPK) { bucket = (unsigned)(c*64 + j); break; }
            cum += h;
        }
        g_bucket   = bucket;
        g_cntabove = (unsigned)cum;            // count with top16 strictly above bucket
        g_krem     = KEEPK - (unsigned)cum;    // rank remaining inside bucket
    }
}

__global__ void hist2_k(const float* __restrict__ w) {
    unsigned bucket = g_bucket;
    unsigned i = blockIdx.x * blockDim.x + threadIdx.x;
    unsigned stride = gridDim.x * blockDim.x;
    for (; i < NW; i += stride) {
        unsigned key = __float_as_uint(w[i]) & 0x7fffffffu;
        if ((key >> 16) == bucket) atomicAdd(&g_hist2[key & 0xffffu], 1u);
    }
}

__global__ void sel2_k() {
    __shared__ unsigned ssum[1024];
    int t = threadIdx.x;
    unsigned s = 0;
    for (int j = 0; j < 64; j++) s += g_hist2[t*64 + j];
    ssum[t] = s;
    __syncthreads();
    if (t == 0) {
        unsigned krem = g_krem;
        unsigned long long cum = 0;
        int c = 1023;
        for (; c >= 0; c--) {
            if (cum + ssum[c] >= (unsigned long long)krem) break;
            cum += ssum[c];
        }
        unsigned low = 0;
        for (int j = 63; j >= 0; j--) {
            unsigned h = g_hist2[c*64 + j];
            cum += h;
            if (cum >= (unsigned long long)krem) { low = (unsigned)(c*64 + j); break; }
        }
        unsigned bits = (g_bucket << 16) | low;
        g_thresh = __uint_as_float(bits);
        unsigned long long cnt_ge = (unsigned long long)g_cntabove + cum;
        g_active_ratio = (float)((double)cnt_ge / (double)NW);
    }
}

__global__ void weff_k(const float* __restrict__ w) {
    float th = g_thresh;
    unsigned i = blockIdx.x * blockDim.x + threadIdx.x;
    if (i < NW) {
        float v = w[i];
        g_weff[i] = (fabsf(v) >= th) ? v : 0.0f;
    }
}

// ---------------- input projection: drive = x @ w_in + b_in ----------------
// C[M=16384][N=2048], K=512. 64x64 tile, 256 threads, 4x4 per thread.
#define BM 64
#define BN 64
#define BK 16
__global__ void __launch_bounds__(256) drive_k(const float* __restrict__ A,
                                               const float* __restrict__ Bw,
                                               const float* __restrict__ bias) {
    __shared__ float sA[BK][BM + 1];
    __shared__ float sB[BK][BN + 1];
    int bm = blockIdx.y * BM;
    int bn = blockIdx.x * BN;
    int tid = threadIdx.x;
    int tx = tid & 15, ty = tid >> 4;
    float acc[4][4] = {};
    for (int k0 = 0; k0 < DIN; k0 += BK) {
        #pragma unroll
        for (int e = 0; e < 4; e++) {
            int idx = tid + e * 256;
            int m = idx >> 4, k = idx & 15;
            sA[k][m] = A[(size_t)(bm + m) * DIN + k0 + k];
        }
        #pragma unroll
        for (int e = 0; e < 4; e++) {
            int idx = tid + e * 256;
            int k = idx >> 6, n = idx & 63;
            sB[k][n] = Bw[(size_t)(k0 + k) * R + bn + n];
        }
        __syncthreads();
        #pragma unroll
        for (int k = 0; k < BK; k++) {
            float a[4], b[4];
            #pragma unroll
            for (int u = 0; u < 4; u++) a[u] = sA[k][ty*4 + u];
            #pragma unroll
            for (int u = 0; u < 4; u++) b[u] = sB[k][tx*4 + u];
            #pragma unroll
            for (int i = 0; i < 4; i++)
                #pragma unroll
                for (int j = 0; j < 4; j++)
                    acc[i][j] += a[i] * b[j];
        }
        __syncthreads();
    }
    #pragma unroll
    for (int i = 0; i < 4; i++)
        #pragma unroll
        for (int j = 0; j < 4; j++)
            g_drive[(size_t)(bm + ty*4 + i) * R + bn + tx*4 + j] = acc[i][j] + bias[bn + tx*4 + j];
}

// ---------------- recurrent step: phase A  (partial = s_prev @ W_eff, K-split) ----------------
// grid (4 jtiles, 4 bgroups, KS), 128 threads; thread owns 4 j cols x 16 batches.
__device__ __forceinline__ void fma4(float4& a, float s, const float4& w) {
    a.x += s * w.x; a.y += s * w.y; a.z += s * w.z; a.w += s * w.w;
}

__global__ void __launch_bounds__(128) stepA_k() {
    __shared__ __align__(16) float ssh[KSL][16];
    int jt = blockIdx.x, bg = blockIdx.y, ks = blockIdx.z;
    int tid = threadIdx.x;
    int j0 = jt * 512 + tid * 4;
    int i0 = ks * KSL;

    for (int e = tid; e < KSL * 16; e += 128) {
        int i = e >> 4, bb = e & 15;
        ssh[i][bb] = g_St[(size_t)(i0 + i) * BATCH + bg * 16 + bb];
    }
    __syncthreads();

    float4 acc[16];
    #pragma unroll
    for (int bb = 0; bb < 16; bb++) acc[bb] = make_float4(0.f, 0.f, 0.f, 0.f);

    const float* wrow = &g_weff[(size_t)i0 * R + j0];
    #pragma unroll 4
    for (int i = 0; i < KSL; i++) {
        float4 w = *reinterpret_cast<const float4*>(wrow);
        wrow += R;
        const float4* sp = reinterpret_cast<const float4*>(&ssh[i][0]);
        float4 s0 = sp[0], s1 = sp[1], s2 = sp[2], s3 = sp[3];
        fma4(acc[0],  s0.x, w); fma4(acc[1],  s0.y, w); fma4(acc[2],  s0.z, w); fma4(acc[3],  s0.w, w);
        fma4(acc[4],  s1.x, w); fma4(acc[5],  s1.y, w); fma4(acc[6],  s1.z, w); fma4(acc[7],  s1.w, w);
        fma4(acc[8],  s2.x, w); fma4(acc[9],  s2.y, w); fma4(acc[10], s2.z, w); fma4(acc[11], s2.w, w);
        fma4(acc[12], s3.x, w); fma4(acc[13], s3.y, w); fma4(acc[14], s3.z, w); fma4(acc[15], s3.w, w);
    }
    #pragma unroll
    for (int bb = 0; bb < 16; bb++) {
        *reinterpret_cast<float4*>(&g_part[((size_t)ks * BATCH + bg * 16 + bb) * R + j0]) = acc[bb];
    }
}

// ---------------- recurrent step: phase B  (reduce + LIF + spike) ----------------
__global__ void __launch_bounds__(256) stepB_k(int t) {
    int idx = blockIdx.x * 256 + threadIdx.x;     // 0..131071
    int b = idx >> 11;
    int j = idx & (R - 1);

    float sum = g_drive[((size_t)t * BATCH + b) * R + j];
    #pragma unroll
    for (int ks = 0; ks < KS; ks++)
        sum += g_part[((size_t)ks * BATCH + b) * R + j];

    float V = BETA * g_V[idx] + sum;
    float s = (V > 1.0f) ? 1.0f : 0.0f;
    V -= s;
    g_V[idx] = V;
    g_St[(size_t)j * BATCH + b] = s;

    unsigned ballot = __ballot_sync(0xffffffffu, s != 0.0f);
    __shared__ int ssum;
    if (threadIdx.x == 0) ssum = 0;
    __syncthreads();
    if ((threadIdx.x & 31) == 0) {
        g_bits[((size_t)t * BATCH + b) * (R / 32) + (j >> 5)] = ballot;
        atomicAdd(&ssum, __popc(ballot));
    }
    __syncthreads();
    if (threadIdx.x == 0) atomicAdd(&g_spk, (unsigned long long)ssum);
}

// ---------------- logits for all (t,b) from spike bitmasks ----------------
__global__ void __launch_bounds__(128) logits_k(const float* __restrict__ wh,
                                                const float* __restrict__ bh,
                                                float* __restrict__ out) {
    int tb = blockIdx.x;      // t*64 + b
    int d = threadIdx.x;
    __shared__ unsigned bits[64];
    if (d < 64) bits[d] = g_bits[(size_t)tb * 64 + d];
    __syncthreads();
    float acc = bh[d];
    #pragma unroll 1
    for (int w = 0; w < 64; w++) {
        unsigned m = bits[w];
        while (m) {                 // uniform across warp (m from shared)
            int k = __ffs(m) - 1;
            m &= m - 1;
            acc += wh[(size_t)(w * 32 + k) * DOUT + d];
        }
    }
    out[(size_t)tb * DOUT + d] = acc;
}

// ---------------- readout = mean over T ----------------
__global__ void readout_k(const float* __restrict__ logits, float* __restrict__ out) {
    int idx = blockIdx.x * 256 + threadIdx.x;   // 0..8191
    if (idx < BATCH * DOUT) {
        float s = 0.f;
        for (int t = 0; t < T_STEPS; t++) s += logits[(size_t)t * BATCH * DOUT + idx];
        out[idx] = s * (1.0f / T_STEPS);
    }
}

__global__ void scalars_k(float* __restrict__ out) {
    out[0] = (float)((double)g_spk / (double)((size_t)T_STEPS * BATCH * R)); // spike_rate
    out[1] = g_active_ratio;                                                 // active_ratio
}

// ---------------- launch ----------------
extern "C" void kernel_launch(void* const* d_in, const int* in_sizes, int n_in,
                              void* d_out, int out_size) {
    const float* x      = (const float*)d_in[0];
    const float* w_in   = (const float*)d_in[1];
    const float* b_in   = (const float*)d_in[2];
    const float* w_rec  = (const float*)d_in[3];
    const float* w_head = (const float*)d_in[4];
    const float* b_head = (const float*)d_in[5];
    float* out = (float*)d_out;

    void *h1p, *h2p, *vp, *stp, *spkp;
    cudaGetSymbolAddress(&h1p,  g_hist1);
    cudaGetSymbolAddress(&h2p,  g_hist2);
    cudaGetSymbolAddress(&vp,   g_V);
    cudaGetSymbolAddress(&stp,  g_St);
    cudaGetSymbolAddress(&spkp, g_spk);

    cudaMemsetAsync(h1p,  0, 65536 * sizeof(unsigned));
    cudaMemsetAsync(h2p,  0, 65536 * sizeof(unsigned));
    cudaMemsetAsync(vp,   0, BATCH * R * sizeof(float));
    cudaMemsetAsync(stp,  0, R * BATCH * sizeof(float));
    cudaMemsetAsync(spkp, 0, sizeof(unsigned long long));

    // exact top-k threshold
    hist1_k<<<2048, 512>>>(w_rec);
    sel1_k<<<1, 1024>>>();
    hist2_k<<<2048, 512>>>(w_rec);
    sel2_k<<<1, 1024>>>();
    weff_k<<<NW / 256, 256>>>(w_rec);

    // input projection
    drive_k<<<dim3(R / BN, (T_STEPS * BATCH) / BM), 256>>>(x, w_in, b_in);

    // sequential LIF scan
    for (int t = 0; t < T_STEPS; t++) {
        stepA_k<<<dim3(4, 4, KS), 128>>>();
        stepB_k<<<(BATCH * R) / 256, 256>>>(t);
    }

    // outputs: [readout 8192][logits_seq 2097152][spike_rate 1][active_ratio 1]
    float* logits_out = out + BATCH * DOUT;
    logits_k<<<T_STEPS * BATCH, 128>>>(w_head, b_head, logits_out);
    readout_k<<<(BATCH * DOUT + 255) / 256, 256>>>(logits_out, out);
    scalars_k<<<1, 1>>>(out + BATCH * DOUT + (size_t)T_STEPS * BATCH * DOUT);
}